// round 1
// baseline (speedup 1.0000x reference)
#include <cuda_runtime.h>
#include <math.h>

#define KCODES 512
#define CDIM   64
#define BATCH  32
#define HDIM   64
#define WDIM   64
#define NPIX   (BATCH*HDIM*WDIM)   // 131072
#define HW     (HDIM*WDIM)         // 4096
#define CHW    (CDIM*HDIM*WDIM)    // 262144

// Scratch for normalized codebook (allocation-free rule: __device__ globals).
__device__ float g_cbn[KCODES*CDIM];
__device__ float g_cc[KCODES];

// ---------------------------------------------------------------------------
// Kernel 1: normalize codebook rows (dim=1), compute per-row ||c||^2 (post-norm),
// exactly mirroring the reference's fp32 math.
// ---------------------------------------------------------------------------
__global__ void norm_cb_kernel(const float* __restrict__ cb) {
    int k = blockIdx.x * blockDim.x + threadIdx.x;
    if (k >= KCODES) return;
    float row[CDIM];
    float ss = 0.f;
    #pragma unroll
    for (int c = 0; c < CDIM; ++c) {
        row[c] = cb[k*CDIM + c];
        ss += row[c]*row[c];
    }
    float inv = 1.0f / fmaxf(sqrtf(ss), 1e-12f);
    float cc = 0.f;
    #pragma unroll
    for (int c = 0; c < CDIM; ++c) {
        float v = row[c] * inv;
        g_cbn[k*CDIM + c] = v;
        cc += v*v;
    }
    g_cc[k] = cc;
}

// ---------------------------------------------------------------------------
// Packed fp32x2 helpers (Blackwell FFMA2 — 2 fp32 FMAs per issue slot)
// ---------------------------------------------------------------------------
__device__ __forceinline__ unsigned long long pack2(float lo, float hi) {
    unsigned long long r;
    asm("mov.b64 %0, {%1, %2};" : "=l"(r) : "f"(lo), "f"(hi));
    return r;
}
__device__ __forceinline__ unsigned long long ffma2(unsigned long long a,
                                                    unsigned long long b,
                                                    unsigned long long c) {
    unsigned long long d;
    asm("fma.rn.f32x2 %0, %1, %2, %3;" : "=l"(d) : "l"(a), "l"(b), "l"(c));
    return d;
}
__device__ __forceinline__ void unpack2(unsigned long long v, float& lo, float& hi) {
    asm("mov.b64 {%0, %1}, %2;" : "=f"(lo), "=f"(hi) : "l"(v));
}

// ---------------------------------------------------------------------------
// Kernel 2: one thread per pixel (b,h,w).
//   - load x[b,:,h,w] (coalesced across w within a warp), L2-normalize
//   - argmin_k ( ||c_k||^2 - 2 * xn . c_k )   [fp32, first-min tie-break]
//   - write codes[b,:,h,w] = cbn[best], indices[b,h,w] = best
// Codebook lives in 130KB dynamic smem; inner loop is FFMA2-bound.
// ---------------------------------------------------------------------------
__global__ void __launch_bounds__(256, 1)
vq_kernel(const float* __restrict__ x, float* __restrict__ out, int write_idx) {
    extern __shared__ float sh[];
    float* sh_cb = sh;              // KCODES*CDIM floats
    float* sh_cc = sh + KCODES*CDIM;

    int tid = threadIdx.x;
    for (int i = tid; i < KCODES*CDIM; i += 256) sh_cb[i] = g_cbn[i];
    for (int i = tid; i < KCODES; i += 256)      sh_cc[i] = g_cc[i];
    __syncthreads();

    int n = blockIdx.x * 256 + tid;
    int w = n & (WDIM-1);
    int h = (n >> 6) & (HDIM-1);
    int b = n >> 12;
    const float* xb = x + (size_t)b*CHW + h*WDIM + w;

    // load + normalize pixel vector
    float xv[CDIM];
    float ss = 0.f;
    #pragma unroll
    for (int c = 0; c < CDIM; ++c) {
        xv[c] = xb[(size_t)c*HW];
        ss += xv[c]*xv[c];
    }
    float inv = 1.0f / fmaxf(sqrtf(ss), 1e-12f);
    unsigned long long xp[CDIM/2];
    #pragma unroll
    for (int c = 0; c < CDIM/2; ++c)
        xp[c] = pack2(xv[2*c]*inv, xv[2*c+1]*inv);

    float best_d = 3.4e38f;
    int   best_k = 0;

    for (int k = 0; k < KCODES; ++k) {
        const unsigned long long* cbp =
            (const unsigned long long*)(sh_cb + k*CDIM);
        unsigned long long a0 = 0ull, a1 = 0ull;   // packed (0.f, 0.f)
        #pragma unroll
        for (int c = 0; c < CDIM/2; c += 2) {
            a0 = ffma2(xp[c],   cbp[c],   a0);
            a1 = ffma2(xp[c+1], cbp[c+1], a1);
        }
        float l0, h0, l1, h1;
        unpack2(a0, l0, h0);
        unpack2(a1, l1, h1);
        float dot = (l0 + h0) + (l1 + h1);
        float d = fmaf(-2.0f, dot, sh_cc[k]);
        if (d < best_d) { best_d = d; best_k = k; }   // strict < = first-min
    }

    // write codes (coalesced across w per channel)
    float* ob = out + (size_t)b*CHW + h*WDIM + w;
    const float* crow = sh_cb + best_k*CDIM;
    #pragma unroll
    for (int c = 0; c < CDIM; ++c)
        ob[(size_t)c*HW] = crow[c];

    if (write_idx)
        out[(size_t)NPIX*CDIM + n] = (float)best_k;
}

// ---------------------------------------------------------------------------
extern "C" void kernel_launch(void* const* d_in, const int* in_sizes, int n_in,
                              void* d_out, int out_size) {
    // inputs: x [32,64,64,64] (8388608), codebook [512,64] (32768) — detect by size
    const float* x;
    const float* cb;
    if (in_sizes[0] == KCODES*CDIM) {
        cb = (const float*)d_in[0];
        x  = (const float*)d_in[1];
    } else {
        x  = (const float*)d_in[0];
        cb = (const float*)d_in[1];
    }
    float* out = (float*)d_out;

    norm_cb_kernel<<<2, 256>>>(cb);

    int smem = (KCODES*CDIM + KCODES) * (int)sizeof(float);
    cudaFuncSetAttribute(vq_kernel, cudaFuncAttributeMaxDynamicSharedMemorySize, smem);

    int write_idx = (out_size >= NPIX*CDIM + NPIX) ? 1 : 0;
    vq_kernel<<<NPIX/256, 256, smem>>>(x, out, write_idx);
}

// round 2
// speedup vs baseline: 1.0257x; 1.0257x over previous
#include <cuda_runtime.h>
#include <math.h>

#define KCODES 512
#define CDIM   64
#define BATCH  32
#define HDIM   64
#define WDIM   64
#define NPIX   (BATCH*HDIM*WDIM)   // 131072
#define HW     (HDIM*WDIM)         // 4096
#define CHW    (CDIM*HDIM*WDIM)    // 262144

// Scratch for normalized codebook (allocation-free rule: __device__ globals).
__device__ float g_cbn[KCODES*CDIM];
__device__ float g_cc[KCODES];

// ---------------------------------------------------------------------------
// Kernel 1: normalize codebook rows (dim=1), compute per-row ||c||^2 (post-norm)
// ---------------------------------------------------------------------------
__global__ void norm_cb_kernel(const float* __restrict__ cb) {
    int k = blockIdx.x * blockDim.x + threadIdx.x;
    if (k >= KCODES) return;
    float row[CDIM];
    float ss = 0.f;
    #pragma unroll
    for (int c = 0; c < CDIM; ++c) {
        row[c] = cb[k*CDIM + c];
        ss += row[c]*row[c];
    }
    float inv = 1.0f / fmaxf(sqrtf(ss), 1e-12f);
    float cc = 0.f;
    #pragma unroll
    for (int c = 0; c < CDIM; ++c) {
        float v = row[c] * inv;
        g_cbn[k*CDIM + c] = v;
        cc += v*v;
    }
    g_cc[k] = cc;
}

// ---------------------------------------------------------------------------
// Packed fp32x2 helpers (Blackwell FFMA2 — 2 fp32 FMAs per issue slot)
// ---------------------------------------------------------------------------
__device__ __forceinline__ unsigned long long pack2(float lo, float hi) {
    unsigned long long r;
    asm("mov.b64 %0, {%1, %2};" : "=l"(r) : "f"(lo), "f"(hi));
    return r;
}
__device__ __forceinline__ unsigned long long ffma2(unsigned long long a,
                                                    unsigned long long b,
                                                    unsigned long long c) {
    unsigned long long d;
    asm("fma.rn.f32x2 %0, %1, %2, %3;" : "=l"(d) : "l"(a), "l"(b), "l"(c));
    return d;
}
__device__ __forceinline__ unsigned long long add2(unsigned long long a,
                                                   unsigned long long b) {
    unsigned long long d;
    asm("add.rn.f32x2 %0, %1, %2;" : "=l"(d) : "l"(a), "l"(b));
    return d;
}
__device__ __forceinline__ void unpack2(unsigned long long v, float& lo, float& hi) {
    asm("mov.b64 {%0, %1}, %2;" : "=f"(lo), "=f"(hi) : "l"(v));
}

// ---------------------------------------------------------------------------
// Kernel 2: one thread per pixel (b,h,w).
//   - load x[b,:,h,w] (coalesced across w), L2-normalize into 32 packed f32x2
//   - argmin_k ( ||c_k||^2 - 2 * xn . c_k )  [fp32, strict < = first-min]
//   - codebook row read from smem via LDS.128 (ulonglong2): 16 LDS/code/warp
//     so the FMA pipe (32 FFMA2/code) is the sole binding resource.
// ---------------------------------------------------------------------------
__global__ void __launch_bounds__(256, 1)
vq_kernel(const float* __restrict__ x, float* __restrict__ out, int write_idx) {
    extern __shared__ float sh[];
    float* sh_cb = sh;              // KCODES*CDIM floats (rows 256B-aligned)
    float* sh_cc = sh + KCODES*CDIM;

    int tid = threadIdx.x;
    // fill smem with 128-bit stores
    {
        const float4* src = (const float4*)g_cbn;
        float4* dst = (float4*)sh_cb;
        #pragma unroll
        for (int i = tid; i < KCODES*CDIM/4; i += 256) dst[i] = src[i];
        for (int i = tid; i < KCODES; i += 256) sh_cc[i] = g_cc[i];
    }
    __syncthreads();

    int n = blockIdx.x * 256 + tid;
    int w = n & (WDIM-1);
    int h = (n >> 6) & (HDIM-1);
    int b = n >> 12;
    const float* xb = x + (size_t)b*CHW + h*WDIM + w;

    // load + normalize pixel vector
    float xv[CDIM];
    float ss = 0.f;
    #pragma unroll
    for (int c = 0; c < CDIM; ++c) {
        xv[c] = xb[(size_t)c*HW];
        ss += xv[c]*xv[c];
    }
    float inv = 1.0f / fmaxf(sqrtf(ss), 1e-12f);
    unsigned long long xp[CDIM/2];
    #pragma unroll
    for (int c = 0; c < CDIM/2; ++c)
        xp[c] = pack2(xv[2*c]*inv, xv[2*c+1]*inv);

    float best_d = 3.4e38f;
    int   best_k = 0;

    #pragma unroll 2
    for (int k = 0; k < KCODES; ++k) {
        const ulonglong2* cbp = (const ulonglong2*)(sh_cb + k*CDIM); // 16 x 16B
        unsigned long long a0 = 0ull, a1 = 0ull, a2 = 0ull, a3 = 0ull;
        #pragma unroll
        for (int i = 0; i < 16; i += 2) {
            ulonglong2 v0 = cbp[i];
            ulonglong2 v1 = cbp[i+1];
            a0 = ffma2(xp[2*i+0], v0.x, a0);
            a1 = ffma2(xp[2*i+1], v0.y, a1);
            a2 = ffma2(xp[2*i+2], v1.x, a2);
            a3 = ffma2(xp[2*i+3], v1.y, a3);
        }
        unsigned long long t0 = add2(a0, a2);
        unsigned long long t1 = add2(a1, a3);
        unsigned long long t  = add2(t0, t1);
        float lo, hi;
        unpack2(t, lo, hi);
        float dot = lo + hi;
        float d = fmaf(-2.0f, dot, sh_cc[k]);
        if (d < best_d) { best_d = d; best_k = k; }   // strict < = first-min
    }

    // write codes (coalesced across w per channel)
    float* ob = out + (size_t)b*CHW + h*WDIM + w;
    const float* crow = sh_cb + best_k*CDIM;
    #pragma unroll
    for (int c = 0; c < CDIM; ++c)
        ob[(size_t)c*HW] = crow[c];

    if (write_idx)
        out[(size_t)NPIX*CDIM + n] = (float)best_k;
}

// ---------------------------------------------------------------------------
extern "C" void kernel_launch(void* const* d_in, const int* in_sizes, int n_in,
                              void* d_out, int out_size) {
    const float* x;
    const float* cb;
    if (in_sizes[0] == KCODES*CDIM) {
        cb = (const float*)d_in[0];
        x  = (const float*)d_in[1];
    } else {
        x  = (const float*)d_in[0];
        cb = (const float*)d_in[1];
    }
    float* out = (float*)d_out;

    norm_cb_kernel<<<2, 256>>>(cb);

    int smem = (KCODES*CDIM + KCODES) * (int)sizeof(float);
    cudaFuncSetAttribute(vq_kernel, cudaFuncAttributeMaxDynamicSharedMemorySize, smem);

    int write_idx = (out_size >= NPIX*CDIM + NPIX) ? 1 : 0;
    vq_kernel<<<NPIX/256, 256, smem>>>(x, out, write_idx);
}

// round 3
// speedup vs baseline: 1.4064x; 1.3712x over previous
#include <cuda_runtime.h>
#include <math.h>

#define KCODES 512
#define CDIM   64
#define BATCH  32
#define HDIM   64
#define WDIM   64
#define NPIX   (BATCH*HDIM*WDIM)   // 131072
#define HW     (HDIM*WDIM)         // 4096
#define CHW    (CDIM*HDIM*WDIM)    // 262144
#define PXT    2                   // pixels per thread

// Scratch for normalized codebook (allocation-free rule: __device__ globals).
__device__ float g_cbn[KCODES*CDIM];
__device__ float g_cc[KCODES];

// ---------------------------------------------------------------------------
// Kernel 1: normalize codebook rows (dim=1), per-row ||c||^2 (post-norm)
// ---------------------------------------------------------------------------
__global__ void norm_cb_kernel(const float* __restrict__ cb) {
    int k = blockIdx.x * blockDim.x + threadIdx.x;
    if (k >= KCODES) return;
    float row[CDIM];
    float ss = 0.f;
    #pragma unroll
    for (int c = 0; c < CDIM; ++c) {
        row[c] = cb[k*CDIM + c];
        ss += row[c]*row[c];
    }
    float inv = 1.0f / fmaxf(sqrtf(ss), 1e-12f);
    float cc = 0.f;
    #pragma unroll
    for (int c = 0; c < CDIM; ++c) {
        float v = row[c] * inv;
        g_cbn[k*CDIM + c] = v;
        cc += v*v;
    }
    g_cc[k] = cc;
}

// ---------------------------------------------------------------------------
// Packed fp32x2 helpers
// ---------------------------------------------------------------------------
typedef unsigned long long u64;
__device__ __forceinline__ u64 pack2(float lo, float hi) {
    u64 r; asm("mov.b64 %0, {%1, %2};" : "=l"(r) : "f"(lo), "f"(hi)); return r;
}
__device__ __forceinline__ u64 ffma2(u64 a, u64 b, u64 c) {
    u64 d; asm("fma.rn.f32x2 %0, %1, %2, %3;" : "=l"(d) : "l"(a), "l"(b), "l"(c)); return d;
}
__device__ __forceinline__ u64 add2(u64 a, u64 b) {
    u64 d; asm("add.rn.f32x2 %0, %1, %2;" : "=l"(d) : "l"(a), "l"(b)); return d;
}
__device__ __forceinline__ u64 mul2(u64 a, u64 b) {
    u64 d; asm("mul.rn.f32x2 %0, %1, %2;" : "=l"(d) : "l"(a), "l"(b)); return d;
}
__device__ __forceinline__ void unpack2(u64 v, float& lo, float& hi) {
    asm("mov.b64 {%0, %1}, %2;" : "=f"(lo), "=f"(hi) : "l"(v));
}

// load x[b,:,h,w], L2-normalize, pack into 32 f32x2
__device__ __forceinline__ void load_norm(const float* __restrict__ xb, u64* xp) {
    #pragma unroll
    for (int c = 0; c < CDIM/2; ++c)
        xp[c] = pack2(xb[(size_t)(2*c)*HW], xb[(size_t)(2*c+1)*HW]);
    u64 s0 = 0ull, s1 = 0ull;
    #pragma unroll
    for (int c = 0; c < CDIM/2; c += 2) {
        s0 = ffma2(xp[c],   xp[c],   s0);
        s1 = ffma2(xp[c+1], xp[c+1], s1);
    }
    float l0,h0,l1,h1; unpack2(s0,l0,h0); unpack2(s1,l1,h1);
    float ss = (l0+h0) + (l1+h1);
    float inv = 1.0f / fmaxf(sqrtf(ss), 1e-12f);
    u64 inv2 = pack2(inv, inv);
    #pragma unroll
    for (int c = 0; c < CDIM/2; ++c) xp[c] = mul2(xp[c], inv2);
}

// ---------------------------------------------------------------------------
// Kernel 2: PXT=2 pixels per thread — each codebook LDS is reused for both
// pixels, doubling FMA-per-L1-byte so the fma pipe becomes the binding pipe.
// ---------------------------------------------------------------------------
__global__ void __launch_bounds__(256, 1)
vq_kernel(const float* __restrict__ x, float* __restrict__ out, int write_idx) {
    extern __shared__ float sh[];
    float* sh_cb = sh;              // KCODES*CDIM floats
    float* sh_cc = sh + KCODES*CDIM;

    int tid = threadIdx.x;
    {
        const float4* src = (const float4*)g_cbn;
        float4* dst = (float4*)sh_cb;
        #pragma unroll
        for (int i = tid; i < KCODES*CDIM/4; i += 256) dst[i] = src[i];
        for (int i = tid; i < KCODES; i += 256) sh_cc[i] = g_cc[i];
    }
    __syncthreads();

    // two pixels per thread: n0 and n0+256 (both warp-coalesced)
    int n0 = blockIdx.x * (256*PXT) + tid;
    int n1 = n0 + 256;

    int w0 = n0 & (WDIM-1), h0 = (n0 >> 6) & (HDIM-1), b0 = n0 >> 12;
    int w1 = n1 & (WDIM-1), h1 = (n1 >> 6) & (HDIM-1), b1 = n1 >> 12;
    const float* xb0 = x + (size_t)b0*CHW + h0*WDIM + w0;
    const float* xb1 = x + (size_t)b1*CHW + h1*WDIM + w1;

    u64 xp0[CDIM/2], xp1[CDIM/2];
    load_norm(xb0, xp0);
    load_norm(xb1, xp1);

    float best_d0 = 3.4e38f, best_d1 = 3.4e38f;
    int   best_k0 = 0,       best_k1 = 0;

    for (int k = 0; k < KCODES; ++k) {
        const ulonglong2* cbp = (const ulonglong2*)(sh_cb + k*CDIM); // 16 x 16B
        u64 a0 = 0ull, a1 = 0ull;   // pixel 0, 2 chains
        u64 b0 = 0ull, b1 = 0ull;   // pixel 1, 2 chains
        #pragma unroll
        for (int i = 0; i < 16; i += 2) {
            ulonglong2 v0 = cbp[i];
            ulonglong2 v1 = cbp[i+1];
            a0 = ffma2(xp0[2*i+0], v0.x, a0);
            b0 = ffma2(xp1[2*i+0], v0.x, b0);
            a1 = ffma2(xp0[2*i+1], v0.y, a1);
            b1 = ffma2(xp1[2*i+1], v0.y, b1);
            a0 = ffma2(xp0[2*i+2], v1.x, a0);
            b0 = ffma2(xp1[2*i+2], v1.x, b0);
            a1 = ffma2(xp0[2*i+3], v1.y, a1);
            b1 = ffma2(xp1[2*i+3], v1.y, b1);
        }
        float cc = sh_cc[k];
        {
            u64 t = add2(a0, a1);
            float lo, hi; unpack2(t, lo, hi);
            float d = fmaf(-2.0f, lo + hi, cc);
            if (d < best_d0) { best_d0 = d; best_k0 = k; }
        }
        {
            u64 t = add2(b0, b1);
            float lo, hi; unpack2(t, lo, hi);
            float d = fmaf(-2.0f, lo + hi, cc);
            if (d < best_d1) { best_d1 = d; best_k1 = k; }
        }
    }

    // write codes (coalesced across w per channel) + indices
    {
        float* ob = out + (size_t)b0*CHW + h0*WDIM + w0;
        const float* crow = sh_cb + best_k0*CDIM;
        #pragma unroll
        for (int c = 0; c < CDIM; ++c) ob[(size_t)c*HW] = crow[c];
    }
    {
        float* ob = out + (size_t)b1*CHW + h1*WDIM + w1;
        const float* crow = sh_cb + best_k1*CDIM;
        #pragma unroll
        for (int c = 0; c < CDIM; ++c) ob[(size_t)c*HW] = crow[c];
    }
    if (write_idx) {
        out[(size_t)NPIX*CDIM + n0] = (float)best_k0;
        out[(size_t)NPIX*CDIM + n1] = (float)best_k1;
    }
}

// ---------------------------------------------------------------------------
extern "C" void kernel_launch(void* const* d_in, const int* in_sizes, int n_in,
                              void* d_out, int out_size) {
    const float* x;
    const float* cb;
    if (in_sizes[0] == KCODES*CDIM) {
        cb = (const float*)d_in[0];
        x  = (const float*)d_in[1];
    } else {
        x  = (const float*)d_in[0];
        cb = (const float*)d_in[1];
    }
    float* out = (float*)d_out;

    norm_cb_kernel<<<2, 256>>>(cb);

    int smem = (KCODES*CDIM + KCODES) * (int)sizeof(float);
    cudaFuncSetAttribute(vq_kernel, cudaFuncAttributeMaxDynamicSharedMemorySize, smem);

    int write_idx = (out_size >= NPIX*CDIM + NPIX) ? 1 : 0;
    vq_kernel<<<NPIX/(256*PXT), 256, smem>>>(x, out, write_idx);
}

// round 5
// speedup vs baseline: 2.1295x; 1.5142x over previous
#include <cuda_runtime.h>
#include <cuda_fp16.h>
#include <math.h>
#include <stdint.h>

#define KCODES 512
#define CDIM   64
#define NPIX   131072
#define HW     4096
#define CHW    262144
#define TILE_M 128
#define NTILES (NPIX/TILE_M)   // 1024
#define CBP    72              // fp16 row pad (144B -> conflict-free ldmatrix)
#define XNP    68              // fp32 xn row pad
#define CAP    16
#define MARGIN 4e-3f

// __device__ scratch (allocation-free rule)
__device__ float g_cbn[KCODES*CDIM];   // normalized codebook fp32
__device__ __half g_cbh[KCODES*CDIM];  // normalized codebook fp16
__device__ float g_cc[KCODES];         // ||cbn_k||^2

// ---------------- smem layout ----------------
#define OFF_B    0                       // 512*72*2   = 73728
#define OFF_A    73728                   // 128*72*2   = 18432
#define OFF_XN   92160                   // 128*68*4   = 34816
#define OFF_CC   126976                  // 512*4      = 2048
#define OFF_LIST 129024                  // 128*16*4   = 8192
#define OFF_CNT  137216                  // 128*4      = 512
#define SM_TOTAL 137728

// ---------------- helpers ----------------
__device__ __forceinline__ uint32_t smem_u32(const void* p) {
    uint32_t a;
    asm("{ .reg .u64 t; cvta.to.shared.u64 t, %1; cvt.u32.u64 %0, t; }" : "=r"(a) : "l"(p));
    return a;
}
__device__ __forceinline__ void ldsm4(uint32_t* r, uint32_t addr) {
    asm volatile("ldmatrix.sync.aligned.m8n8.x4.shared.b16 {%0,%1,%2,%3}, [%4];"
                 : "=r"(r[0]), "=r"(r[1]), "=r"(r[2]), "=r"(r[3]) : "r"(addr));
}
__device__ __forceinline__ void mma16816(float* c, const uint32_t* a,
                                         uint32_t b0, uint32_t b1) {
    asm volatile("mma.sync.aligned.m16n8k16.row.col.f32.f16.f16.f32 "
                 "{%0,%1,%2,%3}, {%4,%5,%6,%7}, {%8,%9}, {%0,%1,%2,%3};"
                 : "+f"(c[0]), "+f"(c[1]), "+f"(c[2]), "+f"(c[3])
                 : "r"(a[0]), "r"(a[1]), "r"(a[2]), "r"(a[3]), "r"(b0), "r"(b1));
}

// ---------------------------------------------------------------------------
// Prep: normalize codebook -> fp32 + fp16 copies + ||c||^2
// ---------------------------------------------------------------------------
__global__ void prep_kernel(const float* __restrict__ cb) {
    int k = blockIdx.x * blockDim.x + threadIdx.x;
    if (k >= KCODES) return;
    float row[CDIM];
    float ss = 0.f;
    #pragma unroll
    for (int c = 0; c < CDIM; ++c) { row[c] = cb[k*CDIM + c]; ss += row[c]*row[c]; }
    float inv = 1.0f / fmaxf(sqrtf(ss), 1e-12f);
    float cc = 0.f;
    #pragma unroll
    for (int c = 0; c < CDIM; ++c) {
        float v = row[c] * inv;
        g_cbn[k*CDIM + c] = v;
        g_cbh[k*CDIM + c] = __float2half_rn(v);
        cc += v*v;
    }
    g_cc[k] = cc;
}

// ---------------------------------------------------------------------------
// Main kernel: fp16 mma.sync prune + exact fp32 rescore.
// CTA = 256 threads (8 warps), 128 pixels; warp w handles rows 16w..16w+15.
// ---------------------------------------------------------------------------
__global__ void __launch_bounds__(256, 1)
vq_kernel(const float* __restrict__ x, float* __restrict__ out, int write_idx) {
    extern __shared__ char sm[];
    __half* Bh = (__half*)(sm + OFF_B);
    __half* Ah = (__half*)(sm + OFF_A);
    float*  XN = (float*)(sm + OFF_XN);
    float*  CC = (float*)(sm + OFF_CC);
    int*  LIST = (int*)(sm + OFF_LIST);
    int*   CNT = (int*)(sm + OFF_CNT);

    int tid = threadIdx.x, lane = tid & 31, wid = tid >> 5;
    int tile = blockIdx.x;

    // ---- load fp16 codebook into padded smem (16B chunks, coalesced) ----
    {
        const uint4* src = (const uint4*)g_cbh;   // 4096 x 16B
        #pragma unroll 4
        for (int i = tid; i < 4096; i += 256) {
            int n = i >> 3, q = i & 7;
            *(uint4*)(Bh + n*CBP + q*8) = src[i];
        }
        for (int i = tid; i < KCODES; i += 256) CC[i] = g_cc[i];
        if (tid < TILE_M) CNT[tid] = 0;
    }

    // ---- load x, normalize, write xn (fp32) + A (fp16) ----
    {
        int r = tid >> 1, hc = (tid & 1) * 32;
        int n = tile*TILE_M + r;
        const float* xb = x + (size_t)(n >> 12)*CHW + (n & 4095);
        float v[32];
        float ss = 0.f;
        #pragma unroll
        for (int i = 0; i < 32; ++i) { v[i] = xb[(size_t)(hc+i)*HW]; ss += v[i]*v[i]; }
        ss += __shfl_xor_sync(0xffffffffu, ss, 1);
        float inv = 1.0f / fmaxf(sqrtf(ss), 1e-12f);
        #pragma unroll
        for (int i = 0; i < 32; ++i) { v[i] *= inv; XN[r*XNP + hc + i] = v[i]; }
        #pragma unroll
        for (int i = 0; i < 16; ++i)
            *(__half2*)(Ah + r*CBP + hc + 2*i) = __floats2half2_rn(v[2*i], v[2*i+1]);
    }
    __syncthreads();

    // ---- GEMM (fp16 mma.sync) + approx argmin + candidate pushes ----
    {
        uint32_t smb = smem_u32(sm);
        uint32_t AhB = smb + OFF_A, BhB = smb + OFF_B;
        int r0 = wid * 16;

        // A fragments for 4 ksteps (kept in regs across all n-chunks)
        uint32_t a[4][4];
        {
            int rsel = lane & 15, kh = (lane >> 4) << 3;
            #pragma unroll
            for (int j = 0; j < 4; ++j) {
                uint32_t ad = AhB + (uint32_t)(((r0 + rsel)*CBP + 16*j + kh) * 2);
                ldsm4(a[j], ad);
            }
        }
        int noff = (lane & 7) + ((lane >> 4) << 3);
        int kadd = ((lane >> 3) & 1) << 3;
        int row_lo = r0 + (lane >> 2), row_hi = row_lo + 8;
        float best_lo = 1e30f, best_hi = 1e30f;

        for (int chunk = 0; chunk < 8; ++chunk) {
            float C[8][4];
            #pragma unroll
            for (int t = 0; t < 8; ++t)
                { C[t][0]=0.f; C[t][1]=0.f; C[t][2]=0.f; C[t][3]=0.f; }

            #pragma unroll
            for (int j = 0; j < 4; ++j) {
                #pragma unroll
                for (int tp = 0; tp < 4; ++tp) {
                    int n0 = chunk*64 + tp*16;
                    uint32_t bad = BhB + (uint32_t)(((n0 + noff)*CBP + 16*j + kadd) * 2);
                    uint32_t b[4];
                    ldsm4(b, bad);
                    mma16816(C[2*tp],   a[j], b[0], b[1]);
                    mma16816(C[2*tp+1], a[j], b[2], b[3]);
                }
            }

            int code0base = chunk*64 + 2*(lane & 3);
            #pragma unroll
            for (int t = 0; t < 8; ++t) {
                int c0 = code0base + t*8;
                float cc0 = CC[c0], cc1 = CC[c0+1];
                C[t][0] = fmaf(-2.f, C[t][0], cc0);
                C[t][1] = fmaf(-2.f, C[t][1], cc1);
                C[t][2] = fmaf(-2.f, C[t][2], cc0);
                C[t][3] = fmaf(-2.f, C[t][3], cc1);
                best_lo = fminf(best_lo, fminf(C[t][0], C[t][1]));
                best_hi = fminf(best_hi, fminf(C[t][2], C[t][3]));
            }
            // share running best across the 4 lanes owning this row
            best_lo = fminf(best_lo, __shfl_xor_sync(0xffffffffu, best_lo, 1));
            best_lo = fminf(best_lo, __shfl_xor_sync(0xffffffffu, best_lo, 2));
            best_hi = fminf(best_hi, __shfl_xor_sync(0xffffffffu, best_hi, 1));
            best_hi = fminf(best_hi, __shfl_xor_sync(0xffffffffu, best_hi, 2));
            float thr_lo = best_lo + MARGIN, thr_hi = best_hi + MARGIN;

            #pragma unroll
            for (int t = 0; t < 8; ++t) {
                int c0 = code0base + t*8;
                if (C[t][0] <= thr_lo) { int p = atomicAdd(&CNT[row_lo], 1); if (p < CAP) LIST[row_lo*CAP + p] = c0;   }
                if (C[t][1] <= thr_lo) { int p = atomicAdd(&CNT[row_lo], 1); if (p < CAP) LIST[row_lo*CAP + p] = c0+1; }
                if (C[t][2] <= thr_hi) { int p = atomicAdd(&CNT[row_hi], 1); if (p < CAP) LIST[row_hi*CAP + p] = c0;   }
                if (C[t][3] <= thr_hi) { int p = atomicAdd(&CNT[row_hi], 1); if (p < CAP) LIST[row_hi*CAP + p] = c0+1; }
            }
        }
    }
    __syncthreads();

    // ---- exact fp32 rescore of candidates + output ----
    {
        int r = tid >> 1, par = tid & 1;
        int n = tile*TILE_M + r;
        int cn = CNT[r];
        bool ovf = (cn > CAP);
        if (cn > CAP) cn = CAP;

        const float4* x4 = (const float4*)(XN + r*XNP);
        float bd = 1e30f;
        int   bk = 0x7fffffff;

        if (!ovf) {
            for (int i = par; i < cn; i += 2) {
                int k = LIST[r*CAP + i];
                const float4* cb4 = (const float4*)(g_cbn + (size_t)k*CDIM);
                float d0 = 0.f, d1 = 0.f;
                #pragma unroll
                for (int q = 0; q < 16; q += 2) {
                    float4 xa = x4[q],   ca = cb4[q];
                    float4 xb2 = x4[q+1], cb2 = cb4[q+1];
                    d0 = fmaf(xa.x, ca.x, d0);  d0 = fmaf(xa.y, ca.y, d0);
                    d0 = fmaf(xa.z, ca.z, d0);  d0 = fmaf(xa.w, ca.w, d0);
                    d1 = fmaf(xb2.x, cb2.x, d1); d1 = fmaf(xb2.y, cb2.y, d1);
                    d1 = fmaf(xb2.z, cb2.z, d1); d1 = fmaf(xb2.w, cb2.w, d1);
                }
                float d = fmaf(-2.f, d0 + d1, CC[k]);
                if (d < bd || (d == bd && k < bk)) { bd = d; bk = k; }
            }
        } else {
            // guaranteed-correct fallback: exact scan over all codes
            for (int k = par; k < KCODES; k += 2) {
                const float4* cb4 = (const float4*)(g_cbn + (size_t)k*CDIM);
                float d0 = 0.f;
                #pragma unroll
                for (int q = 0; q < 16; ++q) {
                    float4 xa = x4[q], ca = cb4[q];
                    d0 = fmaf(xa.x, ca.x, d0); d0 = fmaf(xa.y, ca.y, d0);
                    d0 = fmaf(xa.z, ca.z, d0); d0 = fmaf(xa.w, ca.w, d0);
                }
                float d = fmaf(-2.f, d0, CC[k]);
                if (d < bd || (d == bd && k < bk)) { bd = d; bk = k; }
            }
        }
        // combine the pair (lexicographic (d,k) -> first-min tie-break)
        float od = __shfl_xor_sync(0xffffffffu, bd, 1);
        int   ok = __shfl_xor_sync(0xffffffffu, bk, 1);
        if (od < bd || (od == bd && ok < bk)) { bd = od; bk = ok; }

        float* ob = out + (size_t)(n >> 12)*CHW + (n & 4095);
        const float4* cbb = (const float4*)(g_cbn + (size_t)bk*CDIM);
        #pragma unroll
        for (int q = 0; q < 8; ++q) {
            float4 vv = cbb[par*8 + q];
            int c = (par*8 + q) * 4;
            ob[(size_t)(c+0)*HW] = vv.x;
            ob[(size_t)(c+1)*HW] = vv.y;
            ob[(size_t)(c+2)*HW] = vv.z;
            ob[(size_t)(c+3)*HW] = vv.w;
        }
        if (par == 0 && write_idx)
            out[(size_t)NPIX*CDIM + n] = (float)bk;
    }
}

// ---------------------------------------------------------------------------
extern "C" void kernel_launch(void* const* d_in, const int* in_sizes, int n_in,
                              void* d_out, int out_size) {
    const float* x;
    const float* cb;
    if (in_sizes[0] == KCODES*CDIM) {
        cb = (const float*)d_in[0];
        x  = (const float*)d_in[1];
    } else {
        x  = (const float*)d_in[0];
        cb = (const float*)d_in[1];
    }
    float* out = (float*)d_out;

    prep_kernel<<<2, 256>>>(cb);

    cudaFuncSetAttribute(vq_kernel, cudaFuncAttributeMaxDynamicSharedMemorySize, SM_TOTAL);
    int write_idx = (out_size >= NPIX*CDIM + NPIX) ? 1 : 0;
    vq_kernel<<<NTILES, 256, SM_TOTAL>>>(x, out, write_idx);
}